// round 15
// baseline (speedup 1.0000x reference)
#include <cuda_runtime.h>
#include <cuda_bf16.h>
#include <cstdint>

// ---------------- problem constants ----------------
#define Bq     256
#define Tq     16
#define Cq     40
#define Hq     4
#define Dq     10
#define Vq     50257
#define BT     (Bq*Tq)          // 4096
#define VP2    50688            // padded vocab
#define KK     128              // split-K: [xh(40) xl(40) xh(40) 0(8)]
#define CTILE  128              // cols per CTA
#define NCT    393              // ceil(Vq/128)
#define NRT    32               // BT/128
#define NTILES 786              // sum-exp partials per row (64 cols each)
#define THR    256

// ---------------- device scratch ----------------
__device__ float           g_out[BT * Cq];
__device__ __nv_bfloat16   g_Axs[BT * KK];          // A[m][k]
__device__ __nv_bfloat16   g_Wt[(size_t)VP2 * KK];  // B[n][k]
__device__ float           g_psum[(size_t)NTILES * BT];  // TRANSPOSED: [tile][row]
__device__ float           g_tgt[BT];
__device__ float           g_part[16];

// ---------------- SMEM layout (bytes) ----------------
#define STRB     272            // padded A/B row stride in bytes (136 bf16)
#define OFF_BIAS 0              // 128 floats
#define OFF_TGT  512            // 128 ints
#define OFF_A    1024           // 128 x 272
#define OFF_B    35840          // 128 x 272
#define SMEM_SZ  70656
#define CSTR     132            // C staging stride in words (reuses OFF_A region)

// ---------------- PTX helpers ----------------
__device__ __forceinline__ uint32_t smem_u32(const void* p) {
    uint32_t a;
    asm("{ .reg .u64 t; cvta.to.shared.u64 t, %1; cvt.u32.u64 %0, t; }" : "=r"(a) : "l"(p));
    return a;
}
__device__ __forceinline__ void cp16(uint32_t dst, const void* src) {
    asm volatile("cp.async.cg.shared.global [%0], [%1], 16;" :: "r"(dst), "l"(src));
}
__device__ __forceinline__ void cp_commit_wait() {
    asm volatile("cp.async.commit_group;");
    asm volatile("cp.async.wait_group 0;" ::: "memory");
}
__device__ __forceinline__ void ldm_x4(uint32_t& r0, uint32_t& r1, uint32_t& r2, uint32_t& r3,
                                       uint32_t addr) {
    asm volatile("ldmatrix.sync.aligned.m8n8.x4.shared.b16 {%0,%1,%2,%3}, [%4];"
                 : "=r"(r0), "=r"(r1), "=r"(r2), "=r"(r3) : "r"(addr));
}
__device__ __forceinline__ void mma16816(float* c, const uint32_t* a, const uint32_t* b) {
    asm volatile(
        "mma.sync.aligned.m16n8k16.row.col.f32.bf16.bf16.f32 "
        "{%0,%1,%2,%3}, {%4,%5,%6,%7}, {%8,%9}, {%0,%1,%2,%3};"
        : "+f"(c[0]), "+f"(c[1]), "+f"(c[2]), "+f"(c[3])
        : "r"(a[0]), "r"(a[1]), "r"(a[2]), "r"(a[3]), "r"(b[0]), "r"(b[1]));
}

// ---------------- kernel: split lm_W -> g_Wt (B[n][k]) ----------------
__global__ __launch_bounds__(256)
void wprep_kernel(const float* __restrict__ lm_W) {
    int n = blockIdx.x * 256 + threadIdx.x;
    if (n >= VP2) return;
    bool valid = n < Vq;
    __nv_bfloat16 vals[KK];
    #pragma unroll
    for (int k = 0; k < 40; k++) {
        float w = valid ? lm_W[(size_t)k * Vq + n] : 0.f;
        __nv_bfloat16 h = __float2bfloat16(w);
        __nv_bfloat16 l = __float2bfloat16(w - __bfloat162float(h));
        vals[k]      = h;   // pairs with xh
        vals[40 + k] = h;   // pairs with xl
        vals[80 + k] = l;   // pairs with xh
    }
    #pragma unroll
    for (int k = 120; k < 128; k++) vals[k] = __float2bfloat16(0.f);
    const uint4* vp = reinterpret_cast<const uint4*>(vals);
    uint4* dst = reinterpret_cast<uint4*>(&g_Wt[(size_t)n * KK]);
    #pragma unroll
    for (int i = 0; i < 16; i++) dst[i] = vp[i];
}

// ---------------- kernel: embed + attention (one CTA per batch) ----------------
__global__ __launch_bounds__(128)
void attn_kernel(const int* __restrict__ idx,
                 const float* __restrict__ tok_emb,
                 const float* __restrict__ pos_emb,
                 const float* __restrict__ Wqp,
                 const float* __restrict__ Wkp,
                 const float* __restrict__ Wvp) {
    __shared__ float xs[Tq][Cq];
    __shared__ float qs[Hq][Tq][Dq];
    __shared__ float ks[Hq][Tq][Dq];
    __shared__ float vs[Hq][Tq][Dq];
    __shared__ float at[Hq][Tq][Tq];

    int b = blockIdx.x, tid = threadIdx.x;
    for (int i = tid; i < Tq * Cq; i += 128) {
        int t = i / Cq, c = i - t * Cq;
        int tok = idx[b * Tq + t];
        xs[t][c] = tok_emb[(size_t)tok * Cq + c] + pos_emb[t * Cq + c];
    }
    __syncthreads();

    int h = tid >> 5, lane = tid & 31;
    for (int i = lane; i < Tq * Dq; i += 32) {
        int t = i / Dq, d = i - t * Dq;
        float aq = 0.f, ak = 0.f, av = 0.f;
        #pragma unroll
        for (int c = 0; c < Cq; c++) {
            float x = xs[t][c];
            aq = fmaf(x, Wqp[(h * Cq + c) * Dq + d], aq);
            ak = fmaf(x, Wkp[(h * Cq + c) * Dq + d], ak);
            av = fmaf(x, Wvp[(h * Cq + c) * Dq + d], av);
        }
        qs[h][t][d] = aq; ks[h][t][d] = ak; vs[h][t][d] = av;
    }
    __syncwarp();
    for (int i = lane; i < Tq * Tq; i += 32) {
        int t = i / Tq, s = i - t * Tq;
        float a;
        if (s <= t) {
            a = 0.f;
            #pragma unroll
            for (int d = 0; d < Dq; d++) a = fmaf(qs[h][t][d], ks[h][s][d], a);
        } else a = -INFINITY;
        at[h][t][s] = a;
    }
    __syncwarp();
    if (lane < Tq) {
        int t = lane;
        float m = -INFINITY;
        for (int s = 0; s <= t; s++) m = fmaxf(m, at[h][t][s]);
        float sum = 0.f;
        for (int s = 0; s <= t; s++) { float e = expf(at[h][t][s] - m); at[h][t][s] = e; sum += e; }
        float inv = 1.f / sum;
        for (int s = 0; s <= t; s++) at[h][t][s] *= inv;
    }
    __syncwarp();
    for (int i = lane; i < Tq * Dq; i += 32) {
        int t = i / Dq, d = i - t * Dq;
        float a = 0.f;
        for (int s = 0; s <= t; s++) a = fmaf(at[h][t][s], vs[h][s][d], a);
        g_out[((size_t)(b * Tq + t)) * Cq + h * Dq + d] = a;
    }
}

// ---------------- kernel: split attention output rows -> g_Axs ----------------
__global__ __launch_bounds__(256)
void asplit_kernel() {
    int row = blockIdx.x * 256 + threadIdx.x;
    __nv_bfloat16 vals[KK];
    #pragma unroll
    for (int k = 0; k < 40; k++) {
        float x = g_out[(size_t)row * Cq + k];
        __nv_bfloat16 h = __float2bfloat16(x);
        __nv_bfloat16 l = __float2bfloat16(x - __bfloat162float(h));
        vals[k]      = h;
        vals[40 + k] = l;
        vals[80 + k] = h;
    }
    #pragma unroll
    for (int k = 120; k < 128; k++) vals[k] = __float2bfloat16(0.f);
    const uint4* vp = reinterpret_cast<const uint4*>(vals);
    uint4* dst = reinterpret_cast<uint4*>(&g_Axs[(size_t)row * KK]);
    #pragma unroll
    for (int i = 0; i < 16; i++) dst[i] = vp[i];
}

// ---------------- main: HMMA GEMM 128x128, warp-local staged writeback ----------------
__global__ __launch_bounds__(THR)
void mma_kernel(const float* __restrict__ lm_b,
                const int* __restrict__ targets,
                float* __restrict__ logits,
                int write_logits) {
    extern __shared__ char smem[];
    int tid = threadIdx.x, wid = tid >> 5, lane = tid & 31;
    int ctile = blockIdx.x, rtile = blockIdx.y;
    int c0 = ctile * CTILE, r0 = rtile * 128;

    float* s_bias = reinterpret_cast<float*>(smem + OFF_BIAS);
    int*   s_tgt  = reinterpret_cast<int*>(smem + OFF_TGT);
    uint32_t sbase = smem_u32(smem);

    if (tid < 128) {
        int c = c0 + tid;
        s_bias[tid] = (c < Vq) ? lm_b[c] : 0.f;
        s_tgt[tid]  = targets[r0 + tid];
    }

    // async-load A tile 128 x 128 bf16 (padded stride)
    #pragma unroll
    for (int it = 0; it < 8; it++) {
        int i = tid + it * THR;
        int m = i >> 4, k16 = i & 15;
        cp16(sbase + OFF_A + m * STRB + k16 * 16,
             &g_Axs[(size_t)(r0 + m) * KK + k16 * 8]);
    }
    // async-load B tile 128 x 128 bf16
    #pragma unroll
    for (int it = 0; it < 8; it++) {
        int i = tid + it * THR;
        int n = i >> 4, k16 = i & 15;
        cp16(sbase + OFF_B + n * STRB + k16 * 16,
             &g_Wt[(size_t)(c0 + n) * KK + k16 * 8]);
    }
    cp_commit_wait();
    __syncthreads();

    // warp tiling: rows (wid&3)*32, cols (wid>>2)*64
    int mrow0 = (wid & 3) * 32;
    int ncol0 = (wid >> 2) * 64;
    int g = lane >> 2, t = lane & 3;

    uint32_t a_addr0 = sbase + OFF_A + (mrow0 + (lane & 15)) * STRB + (lane >> 4) * 16;
    uint32_t a_addr1 = a_addr0 + 16 * STRB;
    uint32_t b_addr0 = sbase + OFF_B + (ncol0 + ((lane >> 4) << 3) + (lane & 7)) * STRB + ((lane >> 3) & 1) * 16;
    uint32_t b_addr1 = b_addr0 + 16 * STRB;
    uint32_t b_addr2 = b_addr1 + 16 * STRB;
    uint32_t b_addr3 = b_addr2 + 16 * STRB;

    float acc[2][8][4];
    #pragma unroll
    for (int mt = 0; mt < 2; mt++)
        #pragma unroll
        for (int nt = 0; nt < 8; nt++)
            #pragma unroll
            for (int j = 0; j < 4; j++) acc[mt][nt][j] = 0.f;

    #pragma unroll
    for (int ks = 0; ks < 8; ks++) {
        uint32_t ka = ks * 32;
        uint32_t af[2][4];
        ldm_x4(af[0][0], af[0][1], af[0][2], af[0][3], a_addr0 + ka);
        ldm_x4(af[1][0], af[1][1], af[1][2], af[1][3], a_addr1 + ka);
        uint32_t bf[8][2];
        ldm_x4(bf[0][0], bf[0][1], bf[1][0], bf[1][1], b_addr0 + ka);
        ldm_x4(bf[2][0], bf[2][1], bf[3][0], bf[3][1], b_addr1 + ka);
        ldm_x4(bf[4][0], bf[4][1], bf[5][0], bf[5][1], b_addr2 + ka);
        ldm_x4(bf[6][0], bf[6][1], bf[7][0], bf[7][1], b_addr3 + ka);
        #pragma unroll
        for (int nt = 0; nt < 8; nt++) {
            mma16816(acc[0][nt], af[0], bf[nt]);
            mma16816(acc[1][nt], af[1], bf[nt]);
        }
    }

    __syncthreads();   // all warps done reading A/B smem; reuse as C staging

    // -------- phase 1: bias + sum-exp from registers (no max pass),
    //          stage biased logits to this warp's own smem block --------
    float* Cs = reinterpret_cast<float*>(smem + OFF_A);
    int half = wid >> 2;
    int tix = ctile * 2 + half;
    bool fullcols = (c0 + CTILE) <= Vq;

    float2 bs[8];
    #pragma unroll
    for (int nt = 0; nt < 8; nt++)
        bs[nt] = *reinterpret_cast<const float2*>(&s_bias[ncol0 + nt * 8 + 2 * t]);

    #pragma unroll
    for (int mt = 0; mt < 2; mt++) {
        #pragma unroll
        for (int rh = 0; rh < 2; rh++) {
            int rl = mrow0 + mt * 16 + rh * 8 + g;
            int grow = r0 + rl;
            float s = 0.f;
            #pragma unroll
            for (int nt = 0; nt < 8; nt++) {
                float v0 = acc[mt][nt][rh * 2 + 0] + bs[nt].x;
                float v1 = acc[mt][nt][rh * 2 + 1] + bs[nt].y;
                float2 p; p.x = v0; p.y = v1;
                *reinterpret_cast<float2*>(&Cs[rl * CSTR + ncol0 + nt * 8 + 2 * t]) = p;
                if (fullcols) {
                    s += __expf(v0) + __expf(v1);
                } else {
                    int col = c0 + ncol0 + nt * 8 + 2 * t;
                    if (col < Vq)     s += __expf(v0);
                    if (col + 1 < Vq) s += __expf(v1);
                }
            }
            s += __shfl_xor_sync(0xffffffffu, s, 1);
            s += __shfl_xor_sync(0xffffffffu, s, 2);
            // transposed psum: [tile][row] -> 8 active lanes hit consecutive rows (1 wf)
            if (t == 0) g_psum[(size_t)tix * BT + grow] = s;
        }
    }
    __syncwarp();      // warp-local staging visible to all lanes of this warp

    // -------- phase 2: warp-local coalesced writeback (own 32 rows x 64 cols) --------
    if (write_logits) {
        if (fullcols) {
            #pragma unroll
            for (int i = 0; i < 32; i++) {
                int rl = mrow0 + i;
                size_t rowbase = (size_t)(r0 + rl) * (size_t)Vq + c0 + ncol0;
                float v0 = Cs[rl * CSTR + ncol0 + lane];
                float v1 = Cs[rl * CSTR + ncol0 + lane + 32];
                __stcs(&logits[rowbase + lane],      v0);
                __stcs(&logits[rowbase + lane + 32], v1);
            }
        } else {
            for (int i = 0; i < 32; i++) {
                int rl = mrow0 + i;
                size_t rowbase = (size_t)(r0 + rl) * (size_t)Vq;
                int col0w = c0 + ncol0 + lane;
                if (col0w < Vq)
                    __stcs(&logits[rowbase + col0w], Cs[rl * CSTR + ncol0 + lane]);
                if (col0w + 32 < Vq)
                    __stcs(&logits[rowbase + col0w + 32], Cs[rl * CSTR + ncol0 + lane + 32]);
            }
        }
    } else {
        // no logits output: gather target logit from this warp's staged block
        int rl = mrow0 + lane;                 // 32 rows per warp, one per lane
        int tg = s_tgt[rl];
        int lo = c0 + ncol0;
        if (tg >= lo && tg < lo + 64)
            g_tgt[r0 + rl] = Cs[rl * CSTR + (tg - c0)];
    }
}

// ---------------- rowloss: thread per row, coalesced over transposed psum ----------
__global__ __launch_bounds__(256)
void rowloss_kernel(const int* __restrict__ targets,
                    const float* __restrict__ logits,
                    int write_logits) {
    int row = blockIdx.x * 256 + threadIdx.x;   // grid 16 x 256 = 4096
    float s0 = 0.f, s1 = 0.f;
    #pragma unroll 2
    for (int t = 0; t < NTILES - 1; t += 2) {
        s0 += g_psum[(size_t)t * BT + row];
        s1 += g_psum[(size_t)(t + 1) * BT + row];
    }
    // NTILES even (786) -> no tail
    float s = s0 + s1;
    float tgtv = write_logits ? logits[(size_t)row * Vq + targets[row]]
                              : g_tgt[row];
    float l = logf(s) - tgtv;

    __shared__ float sb[256];
    sb[threadIdx.x] = l;
    __syncthreads();
    for (int o = 128; o >= 1; o >>= 1) {
        if (threadIdx.x < o) sb[threadIdx.x] += sb[threadIdx.x + o];
        __syncthreads();
    }
    if (threadIdx.x == 0) g_part[blockIdx.x] = sb[0];
}

__global__ void final_kernel(float* __restrict__ out, int loss_idx, int do_loss) {
    if (!do_loss) return;
    float v = (threadIdx.x < 16) ? g_part[threadIdx.x] : 0.f;
    #pragma unroll
    for (int o = 16; o >= 1; o >>= 1) v += __shfl_xor_sync(0xffffffffu, v, o);
    if (threadIdx.x == 0) out[loss_idx] = v * (1.0f / (float)BT);
}

// ---------------- launch ----------------
extern "C" void kernel_launch(void* const* d_in, const int* in_sizes, int n_in,
                              void* d_out, int out_size) {
    const int*   idx     = (const int*)d_in[0];
    const int*   targets = (const int*)d_in[1];
    const float* tok_emb = (const float*)d_in[2];
    const float* pos_emb = (const float*)d_in[3];
    const float* Wqp     = (const float*)d_in[4];
    const float* Wkp     = (const float*)d_in[5];
    const float* Wvp     = (const float*)d_in[6];
    const float* lm_W    = (const float*)d_in[7];
    const float* lm_b    = (const float*)d_in[8];
    float* out = (float*)d_out;

    const long long LOGITS = (long long)BT * Vq;
    int write_logits = (out_size >= LOGITS) ? 1 : 0;
    int do_loss = 1;
    int loss_idx;
    if (write_logits) {
        if ((long long)out_size > LOGITS) loss_idx = (int)LOGITS;
        else { do_loss = 0; loss_idx = 0; }
    } else {
        loss_idx = out_size - 1;
    }

    cudaFuncSetAttribute(mma_kernel, cudaFuncAttributeMaxDynamicSharedMemorySize, SMEM_SZ);

    wprep_kernel<<<(VP2 + 255) / 256, 256>>>(lm_W);
    attn_kernel<<<Bq, 128>>>(idx, tok_emb, pos_emb, Wqp, Wkp, Wvp);
    asplit_kernel<<<BT / 256, 256>>>();
    mma_kernel<<<dim3(NCT, NRT), THR, SMEM_SZ>>>(lm_b, targets, out, write_logits);
    rowloss_kernel<<<16, 256>>>(targets, out, write_logits);
    final_kernel<<<1, 32>>>(out, loss_idx, do_loss);
}

// round 16
// speedup vs baseline: 1.1557x; 1.1557x over previous
#include <cuda_runtime.h>
#include <cuda_bf16.h>
#include <cstdint>

// ---------------- problem constants ----------------
#define Bq     256
#define Tq     16
#define Cq     40
#define Hq     4
#define Dq     10
#define Vq     50257
#define BT     (Bq*Tq)          // 4096
#define VP2    50688            // padded vocab
#define KK     128              // split-K: [xh(40) xl(40) xh(40) 0(8)]
#define CTILE  128              // cols per CTA
#define NCT    393              // ceil(Vq/128)
#define NRT    32               // BT/128
#define NTILES 786              // sum-exp partials per row (64 cols each)
#define NCHUNK 6                // reduction chunks (786 = 6*131)
#define TPC    131              // tiles per chunk
#define THR    256

// ---------------- device scratch ----------------
__device__ float           g_out[BT * Cq];
__device__ __nv_bfloat16   g_Axs[BT * KK];          // A[m][k]
__device__ __nv_bfloat16   g_Wt[(size_t)VP2 * KK];  // B[n][k]
__device__ float           g_psum[(size_t)NTILES * BT];  // TRANSPOSED: [tile][row]
__device__ float           g_rpart[NCHUNK * BT];
__device__ float           g_tgt[BT];
__device__ float           g_part[16];

// ---------------- SMEM layout (bytes) ----------------
#define STRB     272            // padded A/B row stride in bytes (136 bf16)
#define OFF_BIAS 0              // 128 floats
#define OFF_TGT  512            // 128 ints
#define OFF_A    1024           // 128 x 272
#define OFF_B    35840          // 128 x 272
#define SMEM_SZ  70656
#define CSTR     132            // C staging stride in words (reuses OFF_A region)

// ---------------- PTX helpers ----------------
__device__ __forceinline__ uint32_t smem_u32(const void* p) {
    uint32_t a;
    asm("{ .reg .u64 t; cvta.to.shared.u64 t, %1; cvt.u32.u64 %0, t; }" : "=r"(a) : "l"(p));
    return a;
}
__device__ __forceinline__ void cp16(uint32_t dst, const void* src) {
    asm volatile("cp.async.cg.shared.global [%0], [%1], 16;" :: "r"(dst), "l"(src));
}
__device__ __forceinline__ void cp_commit_wait() {
    asm volatile("cp.async.commit_group;");
    asm volatile("cp.async.wait_group 0;" ::: "memory");
}
__device__ __forceinline__ void ldm_x4(uint32_t& r0, uint32_t& r1, uint32_t& r2, uint32_t& r3,
                                       uint32_t addr) {
    asm volatile("ldmatrix.sync.aligned.m8n8.x4.shared.b16 {%0,%1,%2,%3}, [%4];"
                 : "=r"(r0), "=r"(r1), "=r"(r2), "=r"(r3) : "r"(addr));
}
__device__ __forceinline__ void mma16816(float* c, const uint32_t* a, const uint32_t* b) {
    asm volatile(
        "mma.sync.aligned.m16n8k16.row.col.f32.bf16.bf16.f32 "
        "{%0,%1,%2,%3}, {%4,%5,%6,%7}, {%8,%9}, {%0,%1,%2,%3};"
        : "+f"(c[0]), "+f"(c[1]), "+f"(c[2]), "+f"(c[3])
        : "r"(a[0]), "r"(a[1]), "r"(a[2]), "r"(a[3]), "r"(b[0]), "r"(b[1]));
}

// ---------------- kernel: split lm_W -> g_Wt (B[n][k]) ----------------
__global__ __launch_bounds__(256)
void wprep_kernel(const float* __restrict__ lm_W) {
    int n = blockIdx.x * 256 + threadIdx.x;
    if (n >= VP2) return;
    bool valid = n < Vq;
    __nv_bfloat16 vals[KK];
    #pragma unroll
    for (int k = 0; k < 40; k++) {
        float w = valid ? lm_W[(size_t)k * Vq + n] : 0.f;
        __nv_bfloat16 h = __float2bfloat16(w);
        __nv_bfloat16 l = __float2bfloat16(w - __bfloat162float(h));
        vals[k]      = h;   // pairs with xh
        vals[40 + k] = h;   // pairs with xl
        vals[80 + k] = l;   // pairs with xh
    }
    #pragma unroll
    for (int k = 120; k < 128; k++) vals[k] = __float2bfloat16(0.f);
    const uint4* vp = reinterpret_cast<const uint4*>(vals);
    uint4* dst = reinterpret_cast<uint4*>(&g_Wt[(size_t)n * KK]);
    #pragma unroll
    for (int i = 0; i < 16; i++) dst[i] = vp[i];
}

// ---------------- kernel: embed + attention (one CTA per batch) ----------------
__global__ __launch_bounds__(128)
void attn_kernel(const int* __restrict__ idx,
                 const float* __restrict__ tok_emb,
                 const float* __restrict__ pos_emb,
                 const float* __restrict__ Wqp,
                 const float* __restrict__ Wkp,
                 const float* __restrict__ Wvp) {
    __shared__ float xs[Tq][Cq];
    __shared__ float qs[Hq][Tq][Dq];
    __shared__ float ks[Hq][Tq][Dq];
    __shared__ float vs[Hq][Tq][Dq];
    __shared__ float at[Hq][Tq][Tq];

    int b = blockIdx.x, tid = threadIdx.x;
    for (int i = tid; i < Tq * Cq; i += 128) {
        int t = i / Cq, c = i - t * Cq;
        int tok = idx[b * Tq + t];
        xs[t][c] = tok_emb[(size_t)tok * Cq + c] + pos_emb[t * Cq + c];
    }
    __syncthreads();

    int h = tid >> 5, lane = tid & 31;
    for (int i = lane; i < Tq * Dq; i += 32) {
        int t = i / Dq, d = i - t * Dq;
        float aq = 0.f, ak = 0.f, av = 0.f;
        #pragma unroll
        for (int c = 0; c < Cq; c++) {
            float x = xs[t][c];
            aq = fmaf(x, Wqp[(h * Cq + c) * Dq + d], aq);
            ak = fmaf(x, Wkp[(h * Cq + c) * Dq + d], ak);
            av = fmaf(x, Wvp[(h * Cq + c) * Dq + d], av);
        }
        qs[h][t][d] = aq; ks[h][t][d] = ak; vs[h][t][d] = av;
    }
    __syncwarp();
    for (int i = lane; i < Tq * Tq; i += 32) {
        int t = i / Tq, s = i - t * Tq;
        float a;
        if (s <= t) {
            a = 0.f;
            #pragma unroll
            for (int d = 0; d < Dq; d++) a = fmaf(qs[h][t][d], ks[h][s][d], a);
        } else a = -INFINITY;
        at[h][t][s] = a;
    }
    __syncwarp();
    if (lane < Tq) {
        int t = lane;
        float m = -INFINITY;
        for (int s = 0; s <= t; s++) m = fmaxf(m, at[h][t][s]);
        float sum = 0.f;
        for (int s = 0; s <= t; s++) { float e = expf(at[h][t][s] - m); at[h][t][s] = e; sum += e; }
        float inv = 1.f / sum;
        for (int s = 0; s <= t; s++) at[h][t][s] *= inv;
    }
    __syncwarp();
    for (int i = lane; i < Tq * Dq; i += 32) {
        int t = i / Dq, d = i - t * Dq;
        float a = 0.f;
        for (int s = 0; s <= t; s++) a = fmaf(at[h][t][s], vs[h][s][d], a);
        g_out[((size_t)(b * Tq + t)) * Cq + h * Dq + d] = a;
    }
}

// ---------------- kernel: split attention output rows -> g_Axs ----------------
__global__ __launch_bounds__(256)
void asplit_kernel() {
    int row = blockIdx.x * 256 + threadIdx.x;
    __nv_bfloat16 vals[KK];
    #pragma unroll
    for (int k = 0; k < 40; k++) {
        float x = g_out[(size_t)row * Cq + k];
        __nv_bfloat16 h = __float2bfloat16(x);
        __nv_bfloat16 l = __float2bfloat16(x - __bfloat162float(h));
        vals[k]      = h;
        vals[40 + k] = l;
        vals[80 + k] = h;
    }
    #pragma unroll
    for (int k = 120; k < 128; k++) vals[k] = __float2bfloat16(0.f);
    const uint4* vp = reinterpret_cast<const uint4*>(vals);
    uint4* dst = reinterpret_cast<uint4*>(&g_Axs[(size_t)row * KK]);
    #pragma unroll
    for (int i = 0; i < 16; i++) dst[i] = vp[i];
}

// ---------------- main: HMMA GEMM 128x128, warp-local staged writeback ----------------
__global__ __launch_bounds__(THR)
void mma_kernel(const float* __restrict__ lm_b,
                const int* __restrict__ targets,
                float* __restrict__ logits,
                int write_logits) {
    extern __shared__ char smem[];
    int tid = threadIdx.x, wid = tid >> 5, lane = tid & 31;
    int ctile = blockIdx.x, rtile = blockIdx.y;
    int c0 = ctile * CTILE, r0 = rtile * 128;

    float* s_bias = reinterpret_cast<float*>(smem + OFF_BIAS);
    int*   s_tgt  = reinterpret_cast<int*>(smem + OFF_TGT);
    uint32_t sbase = smem_u32(smem);

    if (tid < 128) {
        int c = c0 + tid;
        s_bias[tid] = (c < Vq) ? lm_b[c] : 0.f;
        s_tgt[tid]  = targets[r0 + tid];
    }

    // async-load A tile 128 x 128 bf16 (padded stride)
    #pragma unroll
    for (int it = 0; it < 8; it++) {
        int i = tid + it * THR;
        int m = i >> 4, k16 = i & 15;
        cp16(sbase + OFF_A + m * STRB + k16 * 16,
             &g_Axs[(size_t)(r0 + m) * KK + k16 * 8]);
    }
    // async-load B tile 128 x 128 bf16
    #pragma unroll
    for (int it = 0; it < 8; it++) {
        int i = tid + it * THR;
        int n = i >> 4, k16 = i & 15;
        cp16(sbase + OFF_B + n * STRB + k16 * 16,
             &g_Wt[(size_t)(c0 + n) * KK + k16 * 8]);
    }
    cp_commit_wait();
    __syncthreads();

    // warp tiling: rows (wid&3)*32, cols (wid>>2)*64
    int mrow0 = (wid & 3) * 32;
    int ncol0 = (wid >> 2) * 64;
    int g = lane >> 2, t = lane & 3;

    uint32_t a_addr0 = sbase + OFF_A + (mrow0 + (lane & 15)) * STRB + (lane >> 4) * 16;
    uint32_t a_addr1 = a_addr0 + 16 * STRB;
    uint32_t b_addr0 = sbase + OFF_B + (ncol0 + ((lane >> 4) << 3) + (lane & 7)) * STRB + ((lane >> 3) & 1) * 16;
    uint32_t b_addr1 = b_addr0 + 16 * STRB;
    uint32_t b_addr2 = b_addr1 + 16 * STRB;
    uint32_t b_addr3 = b_addr2 + 16 * STRB;

    float acc[2][8][4];
    #pragma unroll
    for (int mt = 0; mt < 2; mt++)
        #pragma unroll
        for (int nt = 0; nt < 8; nt++)
            #pragma unroll
            for (int j = 0; j < 4; j++) acc[mt][nt][j] = 0.f;

    #pragma unroll
    for (int ks = 0; ks < 8; ks++) {
        uint32_t ka = ks * 32;
        uint32_t af[2][4];
        ldm_x4(af[0][0], af[0][1], af[0][2], af[0][3], a_addr0 + ka);
        ldm_x4(af[1][0], af[1][1], af[1][2], af[1][3], a_addr1 + ka);
        uint32_t bf[8][2];
        ldm_x4(bf[0][0], bf[0][1], bf[1][0], bf[1][1], b_addr0 + ka);
        ldm_x4(bf[2][0], bf[2][1], bf[3][0], bf[3][1], b_addr1 + ka);
        ldm_x4(bf[4][0], bf[4][1], bf[5][0], bf[5][1], b_addr2 + ka);
        ldm_x4(bf[6][0], bf[6][1], bf[7][0], bf[7][1], b_addr3 + ka);
        #pragma unroll
        for (int nt = 0; nt < 8; nt++) {
            mma16816(acc[0][nt], af[0], bf[nt]);
            mma16816(acc[1][nt], af[1], bf[nt]);
        }
    }

    __syncthreads();   // all warps done reading A/B smem; reuse as C staging

    // -------- phase 1: bias + sum-exp from registers (no max pass),
    //          stage biased logits to this warp's own smem block --------
    float* Cs = reinterpret_cast<float*>(smem + OFF_A);
    int half = wid >> 2;
    int tix = ctile * 2 + half;
    bool fullcols = (c0 + CTILE) <= Vq;

    float2 bs[8];
    #pragma unroll
    for (int nt = 0; nt < 8; nt++)
        bs[nt] = *reinterpret_cast<const float2*>(&s_bias[ncol0 + nt * 8 + 2 * t]);

    #pragma unroll
    for (int mt = 0; mt < 2; mt++) {
        #pragma unroll
        for (int rh = 0; rh < 2; rh++) {
            int rl = mrow0 + mt * 16 + rh * 8 + g;
            int grow = r0 + rl;
            float s = 0.f;
            #pragma unroll
            for (int nt = 0; nt < 8; nt++) {
                float v0 = acc[mt][nt][rh * 2 + 0] + bs[nt].x;
                float v1 = acc[mt][nt][rh * 2 + 1] + bs[nt].y;
                float2 p; p.x = v0; p.y = v1;
                *reinterpret_cast<float2*>(&Cs[rl * CSTR + ncol0 + nt * 8 + 2 * t]) = p;
                if (fullcols) {
                    s += __expf(v0) + __expf(v1);
                } else {
                    int col = c0 + ncol0 + nt * 8 + 2 * t;
                    if (col < Vq)     s += __expf(v0);
                    if (col + 1 < Vq) s += __expf(v1);
                }
            }
            s += __shfl_xor_sync(0xffffffffu, s, 1);
            s += __shfl_xor_sync(0xffffffffu, s, 2);
            // transposed psum: [tile][row] -> 8 active lanes hit consecutive rows (1 wf)
            if (t == 0) g_psum[(size_t)tix * BT + grow] = s;
        }
    }
    __syncwarp();      // warp-local staging visible to all lanes of this warp

    // -------- phase 2: warp-local coalesced writeback (own 32 rows x 64 cols) --------
    if (write_logits) {
        if (fullcols) {
            #pragma unroll
            for (int i = 0; i < 32; i++) {
                int rl = mrow0 + i;
                size_t rowbase = (size_t)(r0 + rl) * (size_t)Vq + c0 + ncol0;
                float v0 = Cs[rl * CSTR + ncol0 + lane];
                float v1 = Cs[rl * CSTR + ncol0 + lane + 32];
                __stcs(&logits[rowbase + lane],      v0);
                __stcs(&logits[rowbase + lane + 32], v1);
            }
        } else {
            for (int i = 0; i < 32; i++) {
                int rl = mrow0 + i;
                size_t rowbase = (size_t)(r0 + rl) * (size_t)Vq;
                int col0w = c0 + ncol0 + lane;
                if (col0w < Vq)
                    __stcs(&logits[rowbase + col0w], Cs[rl * CSTR + ncol0 + lane]);
                if (col0w + 32 < Vq)
                    __stcs(&logits[rowbase + col0w + 32], Cs[rl * CSTR + ncol0 + lane + 32]);
            }
        }
    } else {
        // no logits output: gather target logit from this warp's staged block
        int rl = mrow0 + lane;                 // 32 rows per warp, one per lane
        int tg = s_tgt[rl];
        int lo = c0 + ncol0;
        if (tg >= lo && tg < lo + 64)
            g_tgt[r0 + rl] = Cs[rl * CSTR + (tg - c0)];
    }
}

// ---------------- rowpart: 96 CTAs, partial row-sums over transposed psum ----------
__global__ __launch_bounds__(256)
void rowpart_kernel() {
    int row = blockIdx.x * 256 + threadIdx.x;   // 16 x 256 rows
    int t0  = blockIdx.y * TPC;                 // 6 chunks of 131 tiles
    float s0 = 0.f, s1 = 0.f;
    int t = t0;
    for (; t + 1 < t0 + TPC; t += 2) {
        s0 += g_psum[(size_t)t * BT + row];
        s1 += g_psum[(size_t)(t + 1) * BT + row];
    }
    if (t < t0 + TPC) s0 += g_psum[(size_t)t * BT + row];
    g_rpart[blockIdx.y * BT + row] = s0 + s1;
}

// ---------------- rowloss: combine 6 partials + target, reduce ----------------
__global__ __launch_bounds__(256)
void rowloss_kernel(const int* __restrict__ targets,
                    const float* __restrict__ logits,
                    int write_logits) {
    int row = blockIdx.x * 256 + threadIdx.x;   // grid 16 x 256 = 4096
    float s = 0.f;
    #pragma unroll
    for (int c = 0; c < NCHUNK; c++) s += g_rpart[c * BT + row];
    float tgtv = write_logits ? logits[(size_t)row * Vq + targets[row]]
                              : g_tgt[row];
    float l = logf(s) - tgtv;

    __shared__ float sb[256];
    sb[threadIdx.x] = l;
    __syncthreads();
    for (int o = 128; o >= 1; o >>= 1) {
        if (threadIdx.x < o) sb[threadIdx.x] += sb[threadIdx.x + o];
        __syncthreads();
    }
    if (threadIdx.x == 0) g_part[blockIdx.x] = sb[0];
}

__global__ void final_kernel(float* __restrict__ out, int loss_idx, int do_loss) {
    if (!do_loss) return;
    float v = (threadIdx.x < 16) ? g_part[threadIdx.x] : 0.f;
    #pragma unroll
    for (int o = 16; o >= 1; o >>= 1) v += __shfl_xor_sync(0xffffffffu, v, o);
    if (threadIdx.x == 0) out[loss_idx] = v * (1.0f / (float)BT);
}

// ---------------- launch ----------------
extern "C" void kernel_launch(void* const* d_in, const int* in_sizes, int n_in,
                              void* d_out, int out_size) {
    const int*   idx     = (const int*)d_in[0];
    const int*   targets = (const int*)d_in[1];
    const float* tok_emb = (const float*)d_in[2];
    const float* pos_emb = (const float*)d_in[3];
    const float* Wqp     = (const float*)d_in[4];
    const float* Wkp     = (const float*)d_in[5];
    const float* Wvp     = (const float*)d_in[6];
    const float* lm_W    = (const float*)d_in[7];
    const float* lm_b    = (const float*)d_in[8];
    float* out = (float*)d_out;

    const long long LOGITS = (long long)BT * Vq;
    int write_logits = (out_size >= LOGITS) ? 1 : 0;
    int do_loss = 1;
    int loss_idx;
    if (write_logits) {
        if ((long long)out_size > LOGITS) loss_idx = (int)LOGITS;
        else { do_loss = 0; loss_idx = 0; }
    } else {
        loss_idx = out_size - 1;
    }

    cudaFuncSetAttribute(mma_kernel, cudaFuncAttributeMaxDynamicSharedMemorySize, SMEM_SZ);

    wprep_kernel<<<(VP2 + 255) / 256, 256>>>(lm_W);
    attn_kernel<<<Bq, 128>>>(idx, tok_emb, pos_emb, Wqp, Wkp, Wvp);
    asplit_kernel<<<BT / 256, 256>>>();
    mma_kernel<<<dim3(NCT, NRT), THR, SMEM_SZ>>>(lm_b, targets, out, write_logits);
    rowpart_kernel<<<dim3(16, NCHUNK), 256>>>();
    rowloss_kernel<<<16, 256>>>(targets, out, write_logits);
    final_kernel<<<1, 32>>>(out, loss_idx, do_loss);
}

// round 17
// speedup vs baseline: 1.1703x; 1.0127x over previous
#include <cuda_runtime.h>
#include <cuda_bf16.h>
#include <cstdint>

// ---------------- problem constants ----------------
#define Bq     256
#define Tq     16
#define Cq     40
#define Hq     4
#define Dq     10
#define Vq     50257
#define BT     (Bq*Tq)          // 4096
#define VP2    50688            // padded vocab
#define KK     128              // split-K: [xh(40) xl(40) xh(40) 0(8)]
#define CTILE  128              // cols per CTA
#define NCT    393              // ceil(Vq/128)
#define NRT    32               // BT/128
#define THR    256

// ---------------- device scratch ----------------
__device__ __nv_bfloat16   g_Axs[BT * KK];          // A[m][k]
__device__ __nv_bfloat16   g_Wt[(size_t)VP2 * KK];  // B[n][k]
__device__ float           g_rowsum[BT];            // atomic row sum-exp
__device__ float           g_tgt[BT];
__device__ float           g_part[16];

// ---------------- SMEM layout (bytes) ----------------
#define STRB     272            // padded A/B row stride in bytes (136 bf16)
#define OFF_BIAS 0              // 128 floats
#define OFF_TGT  512            // 128 ints
#define OFF_A    1024           // 128 x 272
#define OFF_B    35840          // 128 x 272
#define SMEM_SZ  70656
#define CSTR     132            // C staging stride in words (reuses OFF_A region)

// ---------------- PTX helpers ----------------
__device__ __forceinline__ uint32_t smem_u32(const void* p) {
    uint32_t a;
    asm("{ .reg .u64 t; cvta.to.shared.u64 t, %1; cvt.u32.u64 %0, t; }" : "=r"(a) : "l"(p));
    return a;
}
__device__ __forceinline__ void cp16(uint32_t dst, const void* src) {
    asm volatile("cp.async.cg.shared.global [%0], [%1], 16;" :: "r"(dst), "l"(src));
}
__device__ __forceinline__ void cp_commit_wait() {
    asm volatile("cp.async.commit_group;");
    asm volatile("cp.async.wait_group 0;" ::: "memory");
}
__device__ __forceinline__ void ldm_x4(uint32_t& r0, uint32_t& r1, uint32_t& r2, uint32_t& r3,
                                       uint32_t addr) {
    asm volatile("ldmatrix.sync.aligned.m8n8.x4.shared.b16 {%0,%1,%2,%3}, [%4];"
                 : "=r"(r0), "=r"(r1), "=r"(r2), "=r"(r3) : "r"(addr));
}
__device__ __forceinline__ void mma16816(float* c, const uint32_t* a, const uint32_t* b) {
    asm volatile(
        "mma.sync.aligned.m16n8k16.row.col.f32.bf16.bf16.f32 "
        "{%0,%1,%2,%3}, {%4,%5,%6,%7}, {%8,%9}, {%0,%1,%2,%3};"
        : "+f"(c[0]), "+f"(c[1]), "+f"(c[2]), "+f"(c[3])
        : "r"(a[0]), "r"(a[1]), "r"(a[2]), "r"(a[3]), "r"(b[0]), "r"(b[1]));
}

// ---------------- kernel: split lm_W -> g_Wt (B[n][k]) + zero g_rowsum ----------------
__global__ __launch_bounds__(256)
void wprep_kernel(const float* __restrict__ lm_W) {
    int n = blockIdx.x * 256 + threadIdx.x;
    if (n < BT) g_rowsum[n] = 0.f;
    if (n >= VP2) return;
    bool valid = n < Vq;
    __nv_bfloat16 vals[KK];
    #pragma unroll
    for (int k = 0; k < 40; k++) {
        float w = valid ? lm_W[(size_t)k * Vq + n] : 0.f;
        __nv_bfloat16 h = __float2bfloat16(w);
        __nv_bfloat16 l = __float2bfloat16(w - __bfloat162float(h));
        vals[k]      = h;   // pairs with xh
        vals[40 + k] = h;   // pairs with xl
        vals[80 + k] = l;   // pairs with xh
    }
    #pragma unroll
    for (int k = 120; k < 128; k++) vals[k] = __float2bfloat16(0.f);
    const uint4* vp = reinterpret_cast<const uint4*>(vals);
    uint4* dst = reinterpret_cast<uint4*>(&g_Wt[(size_t)n * KK]);
    #pragma unroll
    for (int i = 0; i < 16; i++) dst[i] = vp[i];
}

// ---------------- kernel: embed + attention + split (one CTA per batch) ----------------
__global__ __launch_bounds__(128)
void attn_kernel(const int* __restrict__ idx,
                 const float* __restrict__ tok_emb,
                 const float* __restrict__ pos_emb,
                 const float* __restrict__ Wqp,
                 const float* __restrict__ Wkp,
                 const float* __restrict__ Wvp) {
    __shared__ float xs[Tq][Cq];
    __shared__ float qs[Hq][Tq][Dq];
    __shared__ float ks[Hq][Tq][Dq];
    __shared__ float vs[Hq][Tq][Dq];
    __shared__ float at[Hq][Tq][Tq];
    __shared__ float os[Tq][Cq];

    int b = blockIdx.x, tid = threadIdx.x;
    for (int i = tid; i < Tq * Cq; i += 128) {
        int t = i / Cq, c = i - t * Cq;
        int tok = idx[b * Tq + t];
        xs[t][c] = tok_emb[(size_t)tok * Cq + c] + pos_emb[t * Cq + c];
    }
    __syncthreads();

    int h = tid >> 5, lane = tid & 31;
    for (int i = lane; i < Tq * Dq; i += 32) {
        int t = i / Dq, d = i - t * Dq;
        float aq = 0.f, ak = 0.f, av = 0.f;
        #pragma unroll
        for (int c = 0; c < Cq; c++) {
            float x = xs[t][c];
            aq = fmaf(x, Wqp[(h * Cq + c) * Dq + d], aq);
            ak = fmaf(x, Wkp[(h * Cq + c) * Dq + d], ak);
            av = fmaf(x, Wvp[(h * Cq + c) * Dq + d], av);
        }
        qs[h][t][d] = aq; ks[h][t][d] = ak; vs[h][t][d] = av;
    }
    __syncwarp();
    for (int i = lane; i < Tq * Tq; i += 32) {
        int t = i / Tq, s = i - t * Tq;
        float a;
        if (s <= t) {
            a = 0.f;
            #pragma unroll
            for (int d = 0; d < Dq; d++) a = fmaf(qs[h][t][d], ks[h][s][d], a);
        } else a = -INFINITY;
        at[h][t][s] = a;
    }
    __syncwarp();
    if (lane < Tq) {
        int t = lane;
        float m = -INFINITY;
        for (int s = 0; s <= t; s++) m = fmaxf(m, at[h][t][s]);
        float sum = 0.f;
        for (int s = 0; s <= t; s++) { float e = expf(at[h][t][s] - m); at[h][t][s] = e; sum += e; }
        float inv = 1.f / sum;
        for (int s = 0; s <= t; s++) at[h][t][s] *= inv;
    }
    __syncwarp();
    for (int i = lane; i < Tq * Dq; i += 32) {
        int t = i / Dq, d = i - t * Dq;
        float a = 0.f;
        for (int s = 0; s <= t; s++) a = fmaf(at[h][t][s], vs[h][s][d], a);
        os[t][h * Dq + d] = a;
    }
    __syncthreads();

    // fused split: row = tid>>3, 16 k-values per thread (part = tid&7)
    {
        int t = tid >> 3, p = tid & 3;       // 4 parts of 32 j's = 128
        // each thread covers j in [p*32, p*32+32)
        __nv_bfloat16 vals[32];
        #pragma unroll
        for (int jj = 0; jj < 32; jj++) {
            int j = p * 32 + jj;
            float v;
            if (j < 40) {
                v = os[t][j];
                vals[jj] = __float2bfloat16(v);
            } else if (j < 80) {
                v = os[t][j - 40];
                __nv_bfloat16 hh = __float2bfloat16(v);
                vals[jj] = __float2bfloat16(v - __bfloat162float(hh));
            } else if (j < 120) {
                vals[jj] = __float2bfloat16(os[t][j - 80]);
            } else {
                vals[jj] = __float2bfloat16(0.f);
            }
        }
        const uint4* vp = reinterpret_cast<const uint4*>(vals);
        uint4* dst = reinterpret_cast<uint4*>(&g_Axs[(size_t)(b * Tq + (tid >> 3) / 2) * KK]);
        // NOTE: 128 threads / 16 rows = 8 threads per row, but we mapped p in [0,4) above.
        // Re-derive properly: row = tid / 8, part8 = tid % 8 covering 16 j's.
        (void)dst; (void)vp; (void)t;
    }
    // correct mapping: 8 threads per row, 16 j's each
    {
        int t = tid >> 3, p8 = tid & 7;
        __nv_bfloat16 vals[16];
        #pragma unroll
        for (int jj = 0; jj < 16; jj++) {
            int j = p8 * 16 + jj;
            if (j < 40) {
                vals[jj] = __float2bfloat16(os[t][j]);
            } else if (j < 80) {
                float v = os[t][j - 40];
                __nv_bfloat16 hh = __float2bfloat16(v);
                vals[jj] = __float2bfloat16(v - __bfloat162float(hh));
            } else if (j < 120) {
                vals[jj] = __float2bfloat16(os[t][j - 80]);
            } else {
                vals[jj] = __float2bfloat16(0.f);
            }
        }
        const uint4* vp = reinterpret_cast<const uint4*>(vals);
        uint4* dst = reinterpret_cast<uint4*>(&g_Axs[(size_t)(b * Tq + t) * KK + p8 * 16]);
        dst[0] = vp[0];
        dst[1] = vp[1];
    }
}

// ---------------- main: HMMA GEMM 128x128, warp-local staged writeback ----------------
__global__ __launch_bounds__(THR)
void mma_kernel(const float* __restrict__ lm_b,
                const int* __restrict__ targets,
                float* __restrict__ logits,
                int write_logits) {
    extern __shared__ char smem[];
    int tid = threadIdx.x, wid = tid >> 5, lane = tid & 31;
    int ctile = blockIdx.x, rtile = blockIdx.y;
    int c0 = ctile * CTILE, r0 = rtile * 128;

    float* s_bias = reinterpret_cast<float*>(smem + OFF_BIAS);
    int*   s_tgt  = reinterpret_cast<int*>(smem + OFF_TGT);
    uint32_t sbase = smem_u32(smem);

    if (tid < 128) {
        int c = c0 + tid;
        s_bias[tid] = (c < Vq) ? lm_b[c] : 0.f;
        s_tgt[tid]  = targets[r0 + tid];
    }

    // async-load A tile 128 x 128 bf16 (padded stride)
    #pragma unroll
    for (int it = 0; it < 8; it++) {
        int i = tid + it * THR;
        int m = i >> 4, k16 = i & 15;
        cp16(sbase + OFF_A + m * STRB + k16 * 16,
             &g_Axs[(size_t)(r0 + m) * KK + k16 * 8]);
    }
    // async-load B tile 128 x 128 bf16
    #pragma unroll
    for (int it = 0; it < 8; it++) {
        int i = tid + it * THR;
        int n = i >> 4, k16 = i & 15;
        cp16(sbase + OFF_B + n * STRB + k16 * 16,
             &g_Wt[(size_t)(c0 + n) * KK + k16 * 8]);
    }
    cp_commit_wait();
    __syncthreads();

    // warp tiling: rows (wid&3)*32, cols (wid>>2)*64
    int mrow0 = (wid & 3) * 32;
    int ncol0 = (wid >> 2) * 64;
    int g = lane >> 2, t = lane & 3;

    uint32_t a_addr0 = sbase + OFF_A + (mrow0 + (lane & 15)) * STRB + (lane >> 4) * 16;
    uint32_t a_addr1 = a_addr0 + 16 * STRB;
    uint32_t b_addr0 = sbase + OFF_B + (ncol0 + ((lane >> 4) << 3) + (lane & 7)) * STRB + ((lane >> 3) & 1) * 16;
    uint32_t b_addr1 = b_addr0 + 16 * STRB;
    uint32_t b_addr2 = b_addr1 + 16 * STRB;
    uint32_t b_addr3 = b_addr2 + 16 * STRB;

    float acc[2][8][4];
    #pragma unroll
    for (int mt = 0; mt < 2; mt++)
        #pragma unroll
        for (int nt = 0; nt < 8; nt++)
            #pragma unroll
            for (int j = 0; j < 4; j++) acc[mt][nt][j] = 0.f;

    #pragma unroll
    for (int ks = 0; ks < 8; ks++) {
        uint32_t ka = ks * 32;
        uint32_t af[2][4];
        ldm_x4(af[0][0], af[0][1], af[0][2], af[0][3], a_addr0 + ka);
        ldm_x4(af[1][0], af[1][1], af[1][2], af[1][3], a_addr1 + ka);
        uint32_t bf[8][2];
        ldm_x4(bf[0][0], bf[0][1], bf[1][0], bf[1][1], b_addr0 + ka);
        ldm_x4(bf[2][0], bf[2][1], bf[3][0], bf[3][1], b_addr1 + ka);
        ldm_x4(bf[4][0], bf[4][1], bf[5][0], bf[5][1], b_addr2 + ka);
        ldm_x4(bf[6][0], bf[6][1], bf[7][0], bf[7][1], b_addr3 + ka);
        #pragma unroll
        for (int nt = 0; nt < 8; nt++) {
            mma16816(acc[0][nt], af[0], bf[nt]);
            mma16816(acc[1][nt], af[1], bf[nt]);
        }
    }

    __syncthreads();   // all warps done reading A/B smem; reuse as C staging

    // -------- phase 1: bias + sum-exp from registers (no max pass),
    //          stage biased logits; row sums go straight to g_rowsum via REDG --------
    float* Cs = reinterpret_cast<float*>(smem + OFF_A);
    bool fullcols = (c0 + CTILE) <= Vq;

    float2 bs[8];
    #pragma unroll
    for (int nt = 0; nt < 8; nt++)
        bs[nt] = *reinterpret_cast<const float2*>(&s_bias[ncol0 + nt * 8 + 2 * t]);

    #pragma unroll
    for (int mt = 0; mt < 2; mt++) {
        #pragma unroll
        for (int rh = 0; rh < 2; rh++) {
            int rl = mrow0 + mt * 16 + rh * 8 + g;
            int grow = r0 + rl;
            float s = 0.f;
            #pragma unroll
            for (int nt = 0; nt < 8; nt++) {
                float v0 = acc[mt][nt][rh * 2 + 0] + bs[nt].x;
                float v1 = acc[mt][nt][rh * 2 + 1] + bs[nt].y;
                float2 p; p.x = v0; p.y = v1;
                *reinterpret_cast<float2*>(&Cs[rl * CSTR + ncol0 + nt * 8 + 2 * t]) = p;
                if (fullcols) {
                    s += __expf(v0) + __expf(v1);
                } else {
                    int col = c0 + ncol0 + nt * 8 + 2 * t;
                    if (col < Vq)     s += __expf(v0);
                    if (col + 1 < Vq) s += __expf(v1);
                }
            }
            s += __shfl_xor_sync(0xffffffffu, s, 1);
            s += __shfl_xor_sync(0xffffffffu, s, 2);
            if (t == 0) atomicAdd(&g_rowsum[grow], s);   // 8 lanes -> 8 consecutive rows
        }
    }
    __syncwarp();      // warp-local staging visible to all lanes of this warp

    // -------- phase 2: warp-local coalesced writeback (own 32 rows x 64 cols) --------
    if (write_logits) {
        if (fullcols) {
            #pragma unroll
            for (int i = 0; i < 32; i++) {
                int rl = mrow0 + i;
                size_t rowbase = (size_t)(r0 + rl) * (size_t)Vq + c0 + ncol0;
                float v0 = Cs[rl * CSTR + ncol0 + lane];
                float v1 = Cs[rl * CSTR + ncol0 + lane + 32];
                __stcs(&logits[rowbase + lane],      v0);
                __stcs(&logits[rowbase + lane + 32], v1);
            }
        } else {
            for (int i = 0; i < 32; i++) {
                int rl = mrow0 + i;
                size_t rowbase = (size_t)(r0 + rl) * (size_t)Vq;
                int col0w = c0 + ncol0 + lane;
                if (col0w < Vq)
                    __stcs(&logits[rowbase + col0w], Cs[rl * CSTR + ncol0 + lane]);
                if (col0w + 32 < Vq)
                    __stcs(&logits[rowbase + col0w + 32], Cs[rl * CSTR + ncol0 + lane + 32]);
            }
        }
    } else {
        // no logits output: gather target logit from this warp's staged block
        int rl = mrow0 + lane;                 // 32 rows per warp, one per lane
        int tg = s_tgt[rl];
        int lo = c0 + ncol0;
        if (tg >= lo && tg < lo + 64)
            g_tgt[r0 + rl] = Cs[rl * CSTR + (tg - c0)];
    }
}

// ---------------- rowloss: thread per row (sum already atomically combined) ----------
__global__ __launch_bounds__(256)
void rowloss_kernel(const int* __restrict__ targets,
                    const float* __restrict__ logits,
                    int write_logits) {
    int row = blockIdx.x * 256 + threadIdx.x;   // grid 16 x 256 = 4096
    float s = g_rowsum[row];
    float tgtv = write_logits ? logits[(size_t)row * Vq + targets[row]]
                              : g_tgt[row];
    float l = logf(s) - tgtv;

    __shared__ float sb[256];
    sb[threadIdx.x] = l;
    __syncthreads();
    for (int o = 128; o >= 1; o >>= 1) {
        if (threadIdx.x < o) sb[threadIdx.x] += sb[threadIdx.x + o];
        __syncthreads();
    }
    if (threadIdx.x == 0) g_part[blockIdx.x] = sb[0];
}

__global__ void final_kernel(float* __restrict__ out, int loss_idx, int do_loss) {
    if (!do_loss) return;
    float v = (threadIdx.x < 16) ? g_part[threadIdx.x] : 0.f;
    #pragma unroll
    for (int o = 16; o >= 1; o >>= 1) v += __shfl_xor_sync(0xffffffffu, v, o);
    if (threadIdx.x == 0) out[loss_idx] = v * (1.0f / (float)BT);
}

// ---------------- launch ----------------
extern "C" void kernel_launch(void* const* d_in, const int* in_sizes, int n_in,
                              void* d_out, int out_size) {
    const int*   idx     = (const int*)d_in[0];
    const int*   targets = (const int*)d_in[1];
    const float* tok_emb = (const float*)d_in[2];
    const float* pos_emb = (const float*)d_in[3];
    const float* Wqp     = (const float*)d_in[4];
    const float* Wkp     = (const float*)d_in[5];
    const float* Wvp     = (const float*)d_in[6];
    const float* lm_W    = (const float*)d_in[7];
    const float* lm_b    = (const float*)d_in[8];
    float* out = (float*)d_out;

    const long long LOGITS = (long long)BT * Vq;
    int write_logits = (out_size >= LOGITS) ? 1 : 0;
    int do_loss = 1;
    int loss_idx;
    if (write_logits) {
        if ((long long)out_size > LOGITS) loss_idx = (int)LOGITS;
        else { do_loss = 0; loss_idx = 0; }
    } else {
        loss_idx = out_size - 1;
    }

    cudaFuncSetAttribute(mma_kernel, cudaFuncAttributeMaxDynamicSharedMemorySize, SMEM_SZ);

    wprep_kernel<<<(VP2 + 255) / 256, 256>>>(lm_W);
    attn_kernel<<<Bq, 128>>>(idx, tok_emb, pos_emb, Wqp, Wkp, Wvp);
    mma_kernel<<<dim3(NCT, NRT), THR, SMEM_SZ>>>(lm_b, targets, out, write_logits);
    rowloss_kernel<<<16, 256>>>(targets, out, write_logits);
    final_kernel<<<1, 32>>>(out, loss_idx, do_loss);
}